// round 1
// baseline (speedup 1.0000x reference)
#include <cuda_runtime.h>

// ---------------- scratch (device globals; no allocation allowed) ----------
#define NMAX  100032
#define ECAP  1664000

__device__ float g_h  [NMAX * 64];   // GEMM output (pre-scaled by dis[row])
__device__ float g_a  [NMAX * 64];   // post-aggregation activations
__device__ float g_dis[NMAX];
__device__ int   g_cnt[NMAX];
__device__ int   g_rptr[NMAX];
__device__ int   g_col[ECAP];
__device__ int   g_bsum[128];

// ---------------- preprocessing kernels ------------------------------------

__global__ void k_zero(int n) {
    int i = blockIdx.x * 256 + threadIdx.x;
    if (i < n) g_cnt[i] = 0;
}

__global__ void k_hist(const int* __restrict__ dst, int E) {
    int e = blockIdx.x * 256 + threadIdx.x;
    if (e < E) atomicAdd(&g_cnt[dst[e]], 1);
}

// block-wide exclusive scan helper (blockDim.x == 1024)
__device__ __forceinline__ int blockscan_excl(int v, int* total) {
    __shared__ int ws[32];
    int lane = threadIdx.x & 31, wid = threadIdx.x >> 5;
    int s = v;
#pragma unroll
    for (int o = 1; o < 32; o <<= 1) {
        int t = __shfl_up_sync(0xffffffffu, s, o);
        if (lane >= o) s += t;
    }
    if (lane == 31) ws[wid] = s;
    __syncthreads();
    if (wid == 0) {
        int u = ws[lane];
#pragma unroll
        for (int o = 1; o < 32; o <<= 1) {
            int t = __shfl_up_sync(0xffffffffu, u, o);
            if (lane >= o) u += t;
        }
        ws[lane] = u;
    }
    __syncthreads();
    int incl = s + (wid ? ws[wid - 1] : 0);
    if (total) *total = ws[31];
    return incl - v;
}

__global__ void k_scan1(int n) {
    int i = blockIdx.x * 1024 + threadIdx.x;
    int v = (i < n) ? g_cnt[i] : 0;
    int tot;
    int ex = blockscan_excl(v, &tot);
    if (i < n) g_rptr[i] = ex;
    if (threadIdx.x == 0) g_bsum[blockIdx.x] = tot;
}

__global__ void k_scan2(int nb) {
    int i = threadIdx.x;
    int v = (i < nb) ? g_bsum[i] : 0;   // reads complete before any writes (barrier inside scan)
    int ex = blockscan_excl(v, nullptr);
    if (i < nb) g_bsum[i] = ex;
}

__global__ void k_scan3(int n) {
    int i = blockIdx.x * 1024 + threadIdx.x;
    if (i < n) g_rptr[i] += g_bsum[blockIdx.x];
}

__global__ void k_dis(int n) {
    int i = blockIdx.x * 256 + threadIdx.x;
    if (i < n) g_dis[i] = rsqrtf((float)(g_cnt[i] + 1));   // +1 self loop; always > 0
}

// CSR fill: post-increment rowptr in place. After this, rptr[i] == inclusive
// scan, so row i spans [i ? rptr[i-1] : 0, rptr[i]).
__global__ void k_fill(const int* __restrict__ src, const int* __restrict__ dst, int E) {
    int e = blockIdx.x * 256 + threadIdx.x;
    if (e < E) {
        int d = dst[e];
        int p = atomicAdd(&g_rptr[d], 1);
        g_col[p] = src[e];
    }
}

// ---------------- GEMM: H[n,64] = (A[n,K] @ W[K,64]) * dis[row] ------------
// Register-blocked: 4 rows x 8 cols per thread; W tile in smem.
template <int K, bool SRC_GLOBAL>
__global__ void __launch_bounds__(256) k_gemm(const float* __restrict__ Ain,
                                              const float* __restrict__ W, int n) {
    __shared__ float sW[K * 64];
    const float* __restrict__ A = SRC_GLOBAL ? (const float*)g_a : Ain;
    int tid = threadIdx.x;
    for (int i = tid; i < K * 16; i += 256)
        ((float4*)sW)[i] = ((const float4*)W)[i];
    __syncthreads();

    int cc = tid & 7;            // 8 col-chunks of 8
    int rg = tid >> 3;           // 32 row-groups of 4
    int row0 = blockIdx.x * 128 + rg * 4;

    float acc[4][8];
#pragma unroll
    for (int r = 0; r < 4; r++)
#pragma unroll
        for (int c = 0; c < 8; c++) acc[r][c] = 0.f;

    bool ok[4];
#pragma unroll
    for (int r = 0; r < 4; r++) ok[r] = (row0 + r) < n;

    for (int k0 = 0; k0 < K; k0 += 4) {
        float4 a[4];
#pragma unroll
        for (int r = 0; r < 4; r++)
            a[r] = ok[r] ? *(const float4*)(A + (size_t)(row0 + r) * K + k0)
                         : make_float4(0.f, 0.f, 0.f, 0.f);
#pragma unroll
        for (int kk = 0; kk < 4; kk++) {
            float4 w0 = *(const float4*)(sW + (k0 + kk) * 64 + cc * 8);
            float4 w1 = *(const float4*)(sW + (k0 + kk) * 64 + cc * 8 + 4);
#pragma unroll
            for (int r = 0; r < 4; r++) {
                float av = (kk == 0) ? a[r].x : (kk == 1) ? a[r].y : (kk == 2) ? a[r].z : a[r].w;
                acc[r][0] = fmaf(av, w0.x, acc[r][0]);
                acc[r][1] = fmaf(av, w0.y, acc[r][1]);
                acc[r][2] = fmaf(av, w0.z, acc[r][2]);
                acc[r][3] = fmaf(av, w0.w, acc[r][3]);
                acc[r][4] = fmaf(av, w1.x, acc[r][4]);
                acc[r][5] = fmaf(av, w1.y, acc[r][5]);
                acc[r][6] = fmaf(av, w1.z, acc[r][6]);
                acc[r][7] = fmaf(av, w1.w, acc[r][7]);
            }
        }
    }

#pragma unroll
    for (int r = 0; r < 4; r++) {
        if (!ok[r]) continue;
        float d = g_dis[row0 + r];
        float4 o0 = make_float4(acc[r][0] * d, acc[r][1] * d, acc[r][2] * d, acc[r][3] * d);
        float4 o1 = make_float4(acc[r][4] * d, acc[r][5] * d, acc[r][6] * d, acc[r][7] * d);
        float* hp = g_h + (size_t)(row0 + r) * 64 + cc * 8;
        *(float4*)hp = o0;
        *(float4*)(hp + 4) = o1;
    }
}

// ---------------- aggregation: warp per dst node ---------------------------
// out[i] = relu( dis[i] * (h'[i] + sum_{src in nbrs} h'[src]) + bias )
// FC=true additionally applies the 64->4 FC + bfc and writes float4 per node.
template <bool FC>
__global__ void __launch_bounds__(256) k_agg(const float* __restrict__ bias,
                                             const float* __restrict__ Wfc,
                                             const float* __restrict__ bfc,
                                             float* __restrict__ out, int n) {
    int w = (blockIdx.x * 256 + threadIdx.x) >> 5;
    int lane = threadIdx.x & 31;
    if (w >= n) return;

    int start = w ? __ldg(&g_rptr[w - 1]) : 0;
    int end = __ldg(&g_rptr[w]);

    const float2* __restrict__ H2 = (const float2*)g_h;
    float2 acc = H2[(size_t)w * 32 + lane];     // self loop contribution

    int e = start;
    for (; e + 4 <= end; e += 4) {
        int s0 = g_col[e], s1 = g_col[e + 1], s2 = g_col[e + 2], s3 = g_col[e + 3];
        float2 v0 = H2[(size_t)s0 * 32 + lane];
        float2 v1 = H2[(size_t)s1 * 32 + lane];
        float2 v2 = H2[(size_t)s2 * 32 + lane];
        float2 v3 = H2[(size_t)s3 * 32 + lane];
        acc.x += (v0.x + v1.x) + (v2.x + v3.x);
        acc.y += (v0.y + v1.y) + (v2.y + v3.y);
    }
    for (; e < end; e++) {
        int s = g_col[e];
        float2 v = H2[(size_t)s * 32 + lane];
        acc.x += v.x;
        acc.y += v.y;
    }

    float d = g_dis[w];
    float2 b = ((const float2*)bias)[lane];
    float ox = fmaxf(fmaf(acc.x, d, b.x), 0.f);
    float oy = fmaxf(fmaf(acc.y, d, b.y), 0.f);

    if (!FC) {
        ((float2*)g_a)[(size_t)w * 32 + lane] = make_float2(ox, oy);
    } else {
        const float4* Wf = (const float4*)Wfc;   // [64][4]
        float4 w0 = Wf[2 * lane], w1 = Wf[2 * lane + 1];
        float4 y;
        y.x = ox * w0.x + oy * w1.x;
        y.y = ox * w0.y + oy * w1.y;
        y.z = ox * w0.z + oy * w1.z;
        y.w = ox * w0.w + oy * w1.w;
#pragma unroll
        for (int o = 16; o; o >>= 1) {
            y.x += __shfl_xor_sync(0xffffffffu, y.x, o);
            y.y += __shfl_xor_sync(0xffffffffu, y.y, o);
            y.z += __shfl_xor_sync(0xffffffffu, y.z, o);
            y.w += __shfl_xor_sync(0xffffffffu, y.w, o);
        }
        if (lane == 0) {
            float4 bf = *(const float4*)bfc;
            ((float4*)out)[w] = make_float4(y.x + bf.x, y.y + bf.y, y.z + bf.z, y.w + bf.w);
        }
    }
}

// ---------------- launch ----------------------------------------------------

extern "C" void kernel_launch(void* const* d_in, const int* in_sizes, int n_in,
                              void* d_out, int out_size) {
    const float* x   = (const float*)d_in[0];
    const int*   ei  = (const int*)d_in[1];
    const float* W1  = (const float*)d_in[2];
    const float* b1  = (const float*)d_in[3];
    const float* W2  = (const float*)d_in[4];
    const float* b2  = (const float*)d_in[5];
    const float* Wfc = (const float*)d_in[6];
    const float* bfc = (const float*)d_in[7];

    int n = in_sizes[0] / 128;
    int E = in_sizes[1] / 2;
    if (n > NMAX) n = NMAX;
    if (E > ECAP) E = ECAP;
    const int* src = ei;
    const int* dst = ei + E;
    int nb = (n + 1023) / 1024;

    k_zero<<<(n + 255) / 256, 256>>>(n);
    k_hist<<<(E + 255) / 256, 256>>>(dst, E);
    k_scan1<<<nb, 1024>>>(n);
    k_scan2<<<1, 1024>>>(nb);
    k_scan3<<<nb, 1024>>>(n);
    k_dis<<<(n + 255) / 256, 256>>>(n);
    k_fill<<<(E + 255) / 256, 256>>>(src, dst, E);

    k_gemm<128, false><<<(n + 127) / 128, 256>>>(x, W1, n);
    k_agg<false><<<(n + 7) / 8, 256>>>(b1, nullptr, nullptr, nullptr, n);
    k_gemm<64, true><<<(n + 127) / 128, 256>>>(nullptr, W2, n);
    k_agg<true><<<(n + 7) / 8, 256>>>(b2, Wfc, bfc, (float*)d_out, n);
}

// round 2
// speedup vs baseline: 1.0312x; 1.0312x over previous
#include <cuda_runtime.h>
#include <cuda_fp16.h>

// ---------------- scratch (device globals; no allocation allowed) ----------
#define NMAX  100032
#define ECAP  1664000

__device__ __half g_h [NMAX * 64];   // GEMM output (pre-scaled by dis[row]), fp16
__device__ __half g_a [NMAX * 64];   // post-aggregation activations, fp16
__device__ float  g_dis[NMAX];
__device__ int    g_cnt[NMAX];
__device__ int    g_rptr[NMAX];
__device__ int    g_col[ECAP];
__device__ int    g_bsum[128];

// ---------------- preprocessing kernels ------------------------------------

__global__ void k_zero(int n) {
    int i = blockIdx.x * 256 + threadIdx.x;
    if (i < n) g_cnt[i] = 0;
}

__global__ void k_hist(const int* __restrict__ dst, int E) {
    int e = blockIdx.x * 256 + threadIdx.x;
    if (e < E) atomicAdd(&g_cnt[dst[e]], 1);
}

// block-wide exclusive scan helper (blockDim.x == 1024)
__device__ __forceinline__ int blockscan_excl(int v, int* total) {
    __shared__ int ws[32];
    int lane = threadIdx.x & 31, wid = threadIdx.x >> 5;
    int s = v;
#pragma unroll
    for (int o = 1; o < 32; o <<= 1) {
        int t = __shfl_up_sync(0xffffffffu, s, o);
        if (lane >= o) s += t;
    }
    if (lane == 31) ws[wid] = s;
    __syncthreads();
    if (wid == 0) {
        int u = ws[lane];
#pragma unroll
        for (int o = 1; o < 32; o <<= 1) {
            int t = __shfl_up_sync(0xffffffffu, u, o);
            if (lane >= o) u += t;
        }
        ws[lane] = u;
    }
    __syncthreads();
    int incl = s + (wid ? ws[wid - 1] : 0);
    if (total) *total = ws[31];
    return incl - v;
}

__global__ void k_scan1(int n) {
    int i = blockIdx.x * 1024 + threadIdx.x;
    int v = (i < n) ? g_cnt[i] : 0;
    int tot;
    int ex = blockscan_excl(v, &tot);
    if (i < n) g_rptr[i] = ex;
    if (threadIdx.x == 0) g_bsum[blockIdx.x] = tot;
}

__global__ void k_scan2(int nb) {
    int i = threadIdx.x;
    int v = (i < nb) ? g_bsum[i] : 0;   // reads complete before writes (barrier inside scan)
    int ex = blockscan_excl(v, nullptr);
    if (i < nb) g_bsum[i] = ex;
}

// fused: rptr += carry; dis = rsqrt(deg+1)
__global__ void k_scan3dis(int n) {
    int i = blockIdx.x * 1024 + threadIdx.x;
    if (i < n) {
        g_rptr[i] += g_bsum[blockIdx.x];
        g_dis[i] = rsqrtf((float)(g_cnt[i] + 1));   // +1 self loop; always > 0
    }
}

// CSR fill: post-increment rowptr in place. After this, rptr[i] == inclusive
// scan, so row i spans [i ? rptr[i-1] : 0, rptr[i]).
__global__ void k_fill(const int* __restrict__ src, const int* __restrict__ dst, int E) {
    int e = blockIdx.x * 256 + threadIdx.x;
    if (e < E) {
        int d = dst[e];
        int p = atomicAdd(&g_rptr[d], 1);
        g_col[p] = src[e];
    }
}

// ---------------- GEMM: H[n,64] = (A[n,K] @ W[K,64]) * dis[row] -> fp16 -----
// Register-blocked: 4 rows x 8 cols per thread; W tile in smem.
// HALF_IN: A is fp16 from g_a (layer 2); else fp32 from Ain (layer 1).
template <int K, bool HALF_IN>
__global__ void __launch_bounds__(256) k_gemm(const float* __restrict__ Ain,
                                              const float* __restrict__ W, int n) {
    __shared__ float sW[K * 64];
    int tid = threadIdx.x;
    for (int i = tid; i < K * 16; i += 256)
        ((float4*)sW)[i] = ((const float4*)W)[i];
    __syncthreads();

    int cc = tid & 7;            // 8 col-chunks of 8
    int rg = tid >> 3;           // 32 row-groups of 4
    int row0 = blockIdx.x * 128 + rg * 4;

    float acc[4][8];
#pragma unroll
    for (int r = 0; r < 4; r++)
#pragma unroll
        for (int c = 0; c < 8; c++) acc[r][c] = 0.f;

    bool ok[4];
#pragma unroll
    for (int r = 0; r < 4; r++) ok[r] = (row0 + r) < n;

    for (int k0 = 0; k0 < K; k0 += 8) {
        float a8[4][8];
#pragma unroll
        for (int r = 0; r < 4; r++) {
            if (HALF_IN) {
                uint4 u = ok[r] ? *(const uint4*)(g_a + (size_t)(row0 + r) * K + k0)
                                : make_uint4(0, 0, 0, 0);
                float2 f0 = __half22float2(*(__half2*)&u.x);
                float2 f1 = __half22float2(*(__half2*)&u.y);
                float2 f2 = __half22float2(*(__half2*)&u.z);
                float2 f3 = __half22float2(*(__half2*)&u.w);
                a8[r][0] = f0.x; a8[r][1] = f0.y; a8[r][2] = f1.x; a8[r][3] = f1.y;
                a8[r][4] = f2.x; a8[r][5] = f2.y; a8[r][6] = f3.x; a8[r][7] = f3.y;
            } else {
                float4 v0 = ok[r] ? *(const float4*)(Ain + (size_t)(row0 + r) * K + k0)
                                  : make_float4(0.f, 0.f, 0.f, 0.f);
                float4 v1 = ok[r] ? *(const float4*)(Ain + (size_t)(row0 + r) * K + k0 + 4)
                                  : make_float4(0.f, 0.f, 0.f, 0.f);
                a8[r][0] = v0.x; a8[r][1] = v0.y; a8[r][2] = v0.z; a8[r][3] = v0.w;
                a8[r][4] = v1.x; a8[r][5] = v1.y; a8[r][6] = v1.z; a8[r][7] = v1.w;
            }
        }
#pragma unroll
        for (int kk = 0; kk < 8; kk++) {
            float4 w0 = *(const float4*)(sW + (k0 + kk) * 64 + cc * 8);
            float4 w1 = *(const float4*)(sW + (k0 + kk) * 64 + cc * 8 + 4);
#pragma unroll
            for (int r = 0; r < 4; r++) {
                float av = a8[r][kk];
                acc[r][0] = fmaf(av, w0.x, acc[r][0]);
                acc[r][1] = fmaf(av, w0.y, acc[r][1]);
                acc[r][2] = fmaf(av, w0.z, acc[r][2]);
                acc[r][3] = fmaf(av, w0.w, acc[r][3]);
                acc[r][4] = fmaf(av, w1.x, acc[r][4]);
                acc[r][5] = fmaf(av, w1.y, acc[r][5]);
                acc[r][6] = fmaf(av, w1.z, acc[r][6]);
                acc[r][7] = fmaf(av, w1.w, acc[r][7]);
            }
        }
    }

#pragma unroll
    for (int r = 0; r < 4; r++) {
        if (!ok[r]) continue;
        float d = g_dis[row0 + r];
        uint4 o;
        __half2 h0 = __floats2half2_rn(acc[r][0] * d, acc[r][1] * d);
        __half2 h1 = __floats2half2_rn(acc[r][2] * d, acc[r][3] * d);
        __half2 h2 = __floats2half2_rn(acc[r][4] * d, acc[r][5] * d);
        __half2 h3 = __floats2half2_rn(acc[r][6] * d, acc[r][7] * d);
        o.x = *(unsigned*)&h0; o.y = *(unsigned*)&h1;
        o.z = *(unsigned*)&h2; o.w = *(unsigned*)&h3;
        *(uint4*)(g_h + (size_t)(row0 + r) * 64 + cc * 8) = o;
    }
}

// ---------------- aggregation: warp per dst node ---------------------------
// out[i] = relu( dis[i] * (h'[i] + sum_{src in nbrs} h'[src]) + bias )
// h' rows are fp16 (128B/row, one half2 per lane). Accumulate fp32.
// FC=true additionally applies the 64->4 FC + bfc and writes float4 per node.
template <bool FC>
__global__ void __launch_bounds__(256) k_agg(const float* __restrict__ bias,
                                             const float* __restrict__ Wfc,
                                             const float* __restrict__ bfc,
                                             float* __restrict__ out, int n) {
    int w = (blockIdx.x * 256 + threadIdx.x) >> 5;
    int lane = threadIdx.x & 31;
    if (w >= n) return;

    int start = w ? __ldg(&g_rptr[w - 1]) : 0;
    int end = __ldg(&g_rptr[w]);

    const __half2* __restrict__ H2 = (const __half2*)g_h;
    float2 acc = __half22float2(H2[(size_t)w * 32 + lane]);   // self loop

    int e = start;
    for (; e + 4 <= end; e += 4) {
        int s0 = g_col[e], s1 = g_col[e + 1], s2 = g_col[e + 2], s3 = g_col[e + 3];
        float2 v0 = __half22float2(H2[(size_t)s0 * 32 + lane]);
        float2 v1 = __half22float2(H2[(size_t)s1 * 32 + lane]);
        float2 v2 = __half22float2(H2[(size_t)s2 * 32 + lane]);
        float2 v3 = __half22float2(H2[(size_t)s3 * 32 + lane]);
        acc.x += (v0.x + v1.x) + (v2.x + v3.x);
        acc.y += (v0.y + v1.y) + (v2.y + v3.y);
    }
    for (; e < end; e++) {
        float2 v = __half22float2(H2[(size_t)g_col[e] * 32 + lane]);
        acc.x += v.x;
        acc.y += v.y;
    }

    float d = g_dis[w];
    float2 b = ((const float2*)bias)[lane];
    float ox = fmaxf(fmaf(acc.x, d, b.x), 0.f);
    float oy = fmaxf(fmaf(acc.y, d, b.y), 0.f);

    if (!FC) {
        ((__half2*)g_a)[(size_t)w * 32 + lane] = __floats2half2_rn(ox, oy);
    } else {
        const float4* Wf = (const float4*)Wfc;   // [64][4]
        float4 w0 = Wf[2 * lane], w1 = Wf[2 * lane + 1];
        float4 y;
        y.x = ox * w0.x + oy * w1.x;
        y.y = ox * w0.y + oy * w1.y;
        y.z = ox * w0.z + oy * w1.z;
        y.w = ox * w0.w + oy * w1.w;
#pragma unroll
        for (int o = 16; o; o >>= 1) {
            y.x += __shfl_xor_sync(0xffffffffu, y.x, o);
            y.y += __shfl_xor_sync(0xffffffffu, y.y, o);
            y.z += __shfl_xor_sync(0xffffffffu, y.z, o);
            y.w += __shfl_xor_sync(0xffffffffu, y.w, o);
        }
        if (lane == 0) {
            float4 bf = *(const float4*)bfc;
            ((float4*)out)[w] = make_float4(y.x + bf.x, y.y + bf.y, y.z + bf.z, y.w + bf.w);
        }
    }
}

// ---------------- launch ----------------------------------------------------

extern "C" void kernel_launch(void* const* d_in, const int* in_sizes, int n_in,
                              void* d_out, int out_size) {
    const float* x   = (const float*)d_in[0];
    const int*   ei  = (const int*)d_in[1];
    const float* W1  = (const float*)d_in[2];
    const float* b1  = (const float*)d_in[3];
    const float* W2  = (const float*)d_in[4];
    const float* b2  = (const float*)d_in[5];
    const float* Wfc = (const float*)d_in[6];
    const float* bfc = (const float*)d_in[7];

    int n = in_sizes[0] / 128;
    int E = in_sizes[1] / 2;
    if (n > NMAX) n = NMAX;
    if (E > ECAP) E = ECAP;
    const int* src = ei;
    const int* dst = ei + E;
    int nb = (n + 1023) / 1024;

    k_zero<<<(n + 255) / 256, 256>>>(n);
    k_hist<<<(E + 255) / 256, 256>>>(dst, E);
    k_scan1<<<nb, 1024>>>(n);
    k_scan2<<<1, 1024>>>(nb);
    k_scan3dis<<<nb, 1024>>>(n);
    k_fill<<<(E + 255) / 256, 256>>>(src, dst, E);

    k_gemm<128, false><<<(n + 127) / 128, 256>>>(x, W1, n);
    k_agg<false><<<(n + 7) / 8, 256>>>(b1, nullptr, nullptr, nullptr, n);
    k_gemm<64, true><<<(n + 127) / 128, 256>>>(nullptr, W2, n);
    k_agg<true><<<(n + 7) / 8, 256>>>(b2, Wfc, bfc, (float*)d_out, n);
}